// round 2
// baseline (speedup 1.0000x reference)
#include <cuda_runtime.h>

// Problem constants
#define TPc   4
#define WSZ   16
#define B_    8
#define F_    256
#define K_    64
#define EDv   256
#define fF    64      // F / TP
#define nWc   4       // K / WSZ
#define Lw    64      // tokens per window
#define NWIN  2048    // B * fF * nWc
#define WTYPES 256    // fF * nWc

// smem strides (floats) chosen for conflict-free mma fragment loads
#define XS_STR 260    // xs: 260 % 32 = 4 -> a-frag banks unique
#define YS_STR 264    // ys: 264 % 32 = 8 -> b-frag banks unique
#define WS_STR 68     // Wsm/As: 68 % 32 = 4 -> conflict-free

// Scratch for A = deg @ edge_bias (4 MB). __device__ global: no allocation.
__device__ float g_A[WTYPES * Lw * Lw];

// ---------------------------------------------------------------------------
// Kernel 0: A[w] = deg[w] @ eb[w], 256 windows of 64x64. fp32 FFMA (matches ref).
// ---------------------------------------------------------------------------
__global__ __launch_bounds__(256) void compute_A_kernel(
    const float* __restrict__ deg, const float* __restrict__ eb)
{
    __shared__ float Ds[64][64];
    __shared__ float Es[64][68];
    int w = blockIdx.x, tid = threadIdx.x;
    const float* D = deg + (size_t)w * 4096;
    const float* E = eb  + (size_t)w * 4096;
    for (int idx = tid; idx < 4096; idx += 256) {
        Ds[idx >> 6][idx & 63] = D[idx];
        Es[idx >> 6][idx & 63] = E[idx];
    }
    __syncthreads();
    int p  = tid >> 2;
    int q0 = (tid & 3) * 16;
    float acc[16];
#pragma unroll
    for (int j = 0; j < 16; j++) acc[j] = 0.f;
    for (int k = 0; k < 64; k++) {
        float a = Ds[p][k];
#pragma unroll
        for (int j = 0; j < 16; j++) acc[j] = fmaf(a, Es[k][q0 + j], acc[j]);
    }
    float* Aout = g_A + (size_t)w * 4096 + p * 64 + q0;
#pragma unroll
    for (int j = 0; j < 16; j++) Aout[j] = acc[j];
}

// ---------------------------------------------------------------------------
// tf32 helpers
// ---------------------------------------------------------------------------
__device__ __forceinline__ unsigned f2tf(float f) {
    unsigned r;
    asm("cvt.rna.tf32.f32 %0, %1;" : "=r"(r) : "f"(f));
    return r;
}

__device__ __forceinline__ void mma_tf32(float c[4],
    unsigned a0, unsigned a1, unsigned a2, unsigned a3,
    unsigned b0, unsigned b1)
{
    asm volatile(
        "mma.sync.aligned.m16n8k8.row.col.f32.tf32.tf32.f32 "
        "{%0,%1,%2,%3}, {%4,%5,%6,%7}, {%8,%9}, {%0,%1,%2,%3};"
        : "+f"(c[0]), "+f"(c[1]), "+f"(c[2]), "+f"(c[3])
        : "r"(a0), "r"(a1), "r"(a2), "r"(a3), "r"(b0), "r"(b1));
}

// ---------------------------------------------------------------------------
// Fused kernel: one CTA per window.
//   gather -> LN -> y = xn @ Wp^T + bp -> z = A_w @ y -> scatter (win-reverse)
// ---------------------------------------------------------------------------
extern __shared__ float smem[];

__global__ __launch_bounds__(256) void fused_kernel(
    const float* __restrict__ x, const float* __restrict__ gamma,
    const float* __restrict__ beta, const float* __restrict__ Wp,
    const float* __restrict__ bp, float* __restrict__ out)
{
    float* xs  = smem;                    // 64 x 260 (xn, later reused for z)
    float* ys  = xs  + 64 * XS_STR;       // 64 x 264 (y)
    float* Wsm = ys  + 64 * YS_STR;       // 256 x 68 (Wp k-chunk, [o][k])
    float* As  = Wsm + 256 * WS_STR;      // 64 x 68  (A_w)
    float* gs  = As  + 64 * WS_STR;       // 256
    float* bs  = gs + 256;                // 256
    float* bps = bs + 256;                // 256

    const int tid  = threadIdx.x;
    const int lane = tid & 31;
    const int wid  = tid >> 5;

    const int n   = blockIdx.x;
    const int b   = n >> 8;      // / WTYPES
    const int w   = n & 255;
    const int fi  = w >> 2;      // / nWc
    const int nwi = w & 3;

    gs[tid]  = gamma[tid];
    bs[tid]  = beta[tid];
    bps[tid] = bp[tid];

    // ---- gather x window (64 tokens x 256 ch), coalesced float4 ----
    for (int l = wid; l < 64; l += 8) {
        int tp = l >> 4, wi = l & 15;
        const float4* src = (const float4*)(x +
            ((size_t)(b * F_ + fi * TPc + tp) * K_ + nwi * WSZ + wi) * EDv);
        float4* dst = (float4*)(xs + l * XS_STR);
        dst[lane]      = src[lane];
        dst[lane + 32] = src[lane + 32];
    }
    __syncthreads();

    // ---- LayerNorm in place (4 threads per token), tf32-round output ----
    {
        int t = tid >> 2, q = tid & 3;
        float* row = xs + t * XS_STR + q * 64;
        float s = 0.f, ss = 0.f;
#pragma unroll
        for (int i = 0; i < 64; i++) { float v = row[i]; s += v; ss = fmaf(v, v, ss); }
        s  += __shfl_xor_sync(0xffffffffu, s, 1);
        ss += __shfl_xor_sync(0xffffffffu, ss, 1);
        s  += __shfl_xor_sync(0xffffffffu, s, 2);
        ss += __shfl_xor_sync(0xffffffffu, ss, 2);
        float mu   = s * (1.f / 256.f);
        float var  = ss * (1.f / 256.f) - mu * mu;
        float rstd = rsqrtf(var + 1e-5f);
        const float* g  = gs + q * 64;
        const float* be = bs + q * 64;
#pragma unroll
        for (int i = 0; i < 64; i++) {
            float v = (row[i] - mu) * rstd * g[i] + be[i];
            row[i] = __uint_as_float(f2tf(v));
        }
    }
    __syncthreads();

    // ---- GEMM1: y(64x256) = xn(64x256) @ Wp^T, warp owns 32 output cols ----
    const int n0 = wid * 32;
    const int r4 = lane >> 2, c4 = lane & 3;
    float acc[4][4][4];
#pragma unroll
    for (int mt = 0; mt < 4; mt++)
#pragma unroll
        for (int nt = 0; nt < 4; nt++)
#pragma unroll
            for (int r = 0; r < 4; r++) acc[mt][nt][r] = 0.f;

    for (int kc = 0; kc < 4; kc++) {
        if (kc) __syncthreads();  // previous Wsm chunk fully consumed
        // stage Wp chunk: [o=0..255][k=kc*64..kc*64+63], tf32-rounded
        for (int idx = tid; idx < 256 * 16; idx += 256) {
            int o = idx >> 4, j = idx & 15;
            float4 v = *(const float4*)(Wp + (size_t)o * EDv + kc * 64 + j * 4);
            float* dst = Wsm + o * WS_STR + j * 4;
            dst[0] = __uint_as_float(f2tf(v.x));
            dst[1] = __uint_as_float(f2tf(v.y));
            dst[2] = __uint_as_float(f2tf(v.z));
            dst[3] = __uint_as_float(f2tf(v.w));
        }
        __syncthreads();

#pragma unroll
        for (int ks = 0; ks < 8; ks++) {
            int kb = kc * 64 + ks * 8;  // column in xs
            unsigned a[4][4];
#pragma unroll
            for (int mt = 0; mt < 4; mt++) {
                const float* base = xs + (mt * 16 + r4) * XS_STR + kb + c4;
                a[mt][0] = __float_as_uint(base[0]);
                a[mt][1] = __float_as_uint(base[8 * XS_STR]);
                a[mt][2] = __float_as_uint(base[4]);
                a[mt][3] = __float_as_uint(base[8 * XS_STR + 4]);
            }
            unsigned bb[4][2];
            int kl = ks * 8;
#pragma unroll
            for (int nt = 0; nt < 4; nt++) {
                const float* base = Wsm + (n0 + nt * 8 + r4) * WS_STR + kl + c4;
                bb[nt][0] = __float_as_uint(base[0]);
                bb[nt][1] = __float_as_uint(base[4]);
            }
#pragma unroll
            for (int mt = 0; mt < 4; mt++)
#pragma unroll
                for (int nt = 0; nt < 4; nt++)
                    mma_tf32(acc[mt][nt], a[mt][0], a[mt][1], a[mt][2], a[mt][3],
                             bb[nt][0], bb[nt][1]);
        }
    }

    // ---- y -> ys (add bias, tf32-round). Warp writes only its own columns. ----
#pragma unroll
    for (int mt = 0; mt < 4; mt++)
#pragma unroll
        for (int nt = 0; nt < 4; nt++) {
            int row = mt * 16 + r4;
            int col = n0 + nt * 8 + c4 * 2;
            float b0 = bps[col], b1 = bps[col + 1];
            ys[row * YS_STR + col]           = __uint_as_float(f2tf(acc[mt][nt][0] + b0));
            ys[row * YS_STR + col + 1]       = __uint_as_float(f2tf(acc[mt][nt][1] + b1));
            ys[(row + 8) * YS_STR + col]     = __uint_as_float(f2tf(acc[mt][nt][2] + b0));
            ys[(row + 8) * YS_STR + col + 1] = __uint_as_float(f2tf(acc[mt][nt][3] + b1));
        }

    // ---- stage A_w (tf32-rounded) ----
    const float* Ag = g_A + (size_t)w * 4096;
    for (int idx = tid; idx < 1024; idx += 256) {
        float4 v = *(const float4*)(Ag + idx * 4);
        float* dst = As + (idx >> 4) * WS_STR + (idx & 15) * 4;
        dst[0] = __uint_as_float(f2tf(v.x));
        dst[1] = __uint_as_float(f2tf(v.y));
        dst[2] = __uint_as_float(f2tf(v.z));
        dst[3] = __uint_as_float(f2tf(v.w));
    }
    __syncthreads();  // As ready; also orders ys writes vs. intra-warp reads

    // ---- GEMM2: z(64x256) = A_w(64x64) @ y(64x256) ----
#pragma unroll
    for (int mt = 0; mt < 4; mt++)
#pragma unroll
        for (int nt = 0; nt < 4; nt++)
#pragma unroll
            for (int r = 0; r < 4; r++) acc[mt][nt][r] = 0.f;

#pragma unroll
    for (int ks = 0; ks < 8; ks++) {
        int kb = ks * 8;
        unsigned a[4][4];
#pragma unroll
        for (int mt = 0; mt < 4; mt++) {
            const float* base = As + (mt * 16 + r4) * WS_STR + kb + c4;
            a[mt][0] = __float_as_uint(base[0]);
            a[mt][1] = __float_as_uint(base[8 * WS_STR]);
            a[mt][2] = __float_as_uint(base[4]);
            a[mt][3] = __float_as_uint(base[8 * WS_STR + 4]);
        }
        unsigned bb[4][2];
#pragma unroll
        for (int nt = 0; nt < 4; nt++) {
            const float* base = ys + (kb + c4) * YS_STR + n0 + nt * 8 + r4;
            bb[nt][0] = __float_as_uint(base[0]);
            bb[nt][1] = __float_as_uint(base[4 * YS_STR]);
        }
#pragma unroll
        for (int mt = 0; mt < 4; mt++)
#pragma unroll
            for (int nt = 0; nt < 4; nt++)
                mma_tf32(acc[mt][nt], a[mt][0], a[mt][1], a[mt][2], a[mt][3],
                         bb[nt][0], bb[nt][1]);
    }

    // ---- stage z into xs (reuse; all warps left GEMM1 at the As barrier) ----
#pragma unroll
    for (int mt = 0; mt < 4; mt++)
#pragma unroll
        for (int nt = 0; nt < 4; nt++) {
            int row = mt * 16 + r4;
            int col = n0 + nt * 8 + c4 * 2;
            xs[row * XS_STR + col]           = acc[mt][nt][0];
            xs[row * XS_STR + col + 1]       = acc[mt][nt][1];
            xs[(row + 8) * XS_STR + col]     = acc[mt][nt][2];
            xs[(row + 8) * XS_STR + col + 1] = acc[mt][nt][3];
        }
    __syncthreads();

    // ---- scatter with window_reverse, coalesced float4 ----
    for (int l = wid; l < 64; l += 8) {
        int tp = l >> 4, wi = l & 15;
        float4* dst = (float4*)(out +
            ((size_t)(b * F_ + fi * TPc + tp) * K_ + nwi * WSZ + wi) * EDv);
        const float4* src = (const float4*)(xs + l * XS_STR);
        dst[lane]      = src[lane];
        dst[lane + 32] = src[lane + 32];
    }
}

// ---------------------------------------------------------------------------
// Launch
// ---------------------------------------------------------------------------
extern "C" void kernel_launch(void* const* d_in, const int* in_sizes, int n_in,
                              void* d_out, int out_size)
{
    const float* x     = (const float*)d_in[0];
    const float* gamma = (const float*)d_in[1];
    const float* beta  = (const float*)d_in[2];
    const float* Wp    = (const float*)d_in[3];
    const float* bp    = (const float*)d_in[4];
    const float* eb    = (const float*)d_in[5];
    const float* deg   = (const float*)d_in[6];
    float* out = (float*)d_out;

    compute_A_kernel<<<WTYPES, 256>>>(deg, eb);

    const int smem_bytes = (64 * XS_STR + 64 * YS_STR + 256 * WS_STR +
                            64 * WS_STR + 3 * 256) * (int)sizeof(float);
    cudaFuncSetAttribute(fused_kernel,
                         cudaFuncAttributeMaxDynamicSharedMemorySize, smem_bytes);
    fused_kernel<<<NWIN, 256, smem_bytes>>>(x, gamma, beta, Wp, bp, out);
}

// round 3
// speedup vs baseline: 1.3086x; 1.3086x over previous
#include <cuda_runtime.h>

// Problem constants
#define TPc   4
#define WSZ   16
#define B_    8
#define F_    256
#define K_    64
#define EDv   256
#define fF    64      // F / TP
#define nWc   4       // K / WSZ
#define Lw    64      // tokens per window
#define NWIN  2048    // B * fF * nWc
#define WTYPES 256    // fF * nWc

// Per-phase strides (floats) for the shared per-window buffer.
//  xn phase: stride 260 (mod 32 = 4)  -> GEMM1 a-frag scalar loads conflict-free
//  y/z phase: stride 264 (mod 32 = 8) -> GEMM2 b-frag loads + float2 stores conflict-free
#define XN_STR 260
#define YZ_STR 264
#define WS_STR 68     // Wsm / As rows (mod 32 = 4) -> b-frag / a-frag conflict-free

// Scratch for A = deg @ edge_bias (4 MB). __device__ global: no allocation.
__device__ float g_A[WTYPES * Lw * Lw];

// ---------------------------------------------------------------------------
// Kernel 0: A[w] = deg[w] @ eb[w], 256 windows of 64x64. fp32 FFMA (matches ref).
// ---------------------------------------------------------------------------
__global__ __launch_bounds__(256) void compute_A_kernel(
    const float* __restrict__ deg, const float* __restrict__ eb)
{
    __shared__ float Ds[64][64];
    __shared__ float Es[64][68];
    int w = blockIdx.x, tid = threadIdx.x;
    const float* D = deg + (size_t)w * 4096;
    const float* E = eb  + (size_t)w * 4096;
    for (int idx = tid; idx < 4096; idx += 256) {
        Ds[idx >> 6][idx & 63] = D[idx];
        Es[idx >> 6][idx & 63] = E[idx];
    }
    __syncthreads();
    int p  = tid >> 2;
    int q0 = (tid & 3) * 16;
    float acc[16];
#pragma unroll
    for (int j = 0; j < 16; j++) acc[j] = 0.f;
    for (int k = 0; k < 64; k++) {
        float a = Ds[p][k];
#pragma unroll
        for (int j = 0; j < 16; j++) acc[j] = fmaf(a, Es[k][q0 + j], acc[j]);
    }
    float* Aout = g_A + (size_t)w * 4096 + p * 64 + q0;
#pragma unroll
    for (int j = 0; j < 16; j++) Aout[j] = acc[j];
}

// ---------------------------------------------------------------------------
// tf32 helpers
// ---------------------------------------------------------------------------
__device__ __forceinline__ unsigned f2tf(float f) {
    unsigned r;
    asm("cvt.rna.tf32.f32 %0, %1;" : "=r"(r) : "f"(f));
    return r;
}

__device__ __forceinline__ void mma_tf32(float c[4],
    unsigned a0, unsigned a1, unsigned a2, unsigned a3,
    unsigned b0, unsigned b1)
{
    asm volatile(
        "mma.sync.aligned.m16n8k8.row.col.f32.tf32.tf32.f32 "
        "{%0,%1,%2,%3}, {%4,%5,%6,%7}, {%8,%9}, {%0,%1,%2,%3};"
        : "+f"(c[0]), "+f"(c[1]), "+f"(c[2]), "+f"(c[3])
        : "r"(a0), "r"(a1), "r"(a2), "r"(a3), "r"(b0), "r"(b1));
}

__device__ __forceinline__ void group_bar(int g) {
    asm volatile("bar.sync %0, 256;" :: "r"(g + 1) : "memory");
}

// ---------------------------------------------------------------------------
// Fused kernel: 512 threads = 2 window-groups of the SAME window-type w
// (b = 2*bp and 2*bp+1). Wsm chunks and A_w are shared across the groups.
// Per window one 64x264 buffer: xn -> y -> z (registers carry across rewrite).
// ---------------------------------------------------------------------------
extern __shared__ float smem[];

__global__ __launch_bounds__(512, 1) void fused_kernel(
    const float* __restrict__ x, const float* __restrict__ gamma,
    const float* __restrict__ beta, const float* __restrict__ Wp,
    const float* __restrict__ bp_, float* __restrict__ out)
{
    float* As  = smem;                           // 64 x 68  (A_w, shared)
    float* Wsm = As  + 64 * WS_STR;              // 256 x 68 (Wp k-chunk, shared)
    float* bufs= Wsm + 256 * WS_STR;             // 2 x (64 x 264)
    float* gs  = bufs + 2 * 64 * YZ_STR;         // 256
    float* bs  = gs + 256;                       // 256
    float* bps = bs + 256;                       // 256

    const int tid  = threadIdx.x;
    const int lane = tid & 31;
    const int g    = tid >> 8;       // window-group 0/1
    const int tl   = tid & 255;      // tid within group
    const int wid  = tl >> 5;        // warp within group (0..7)

    const int w   = blockIdx.x & 255;
    const int bp  = blockIdx.x >> 8;     // 0..3
    const int b   = bp * 2 + g;
    const int fi  = w >> 2;
    const int nwi = w & 3;

    float* buf = bufs + g * 64 * YZ_STR;

    if (tid < 256) {
        gs[tid]  = gamma[tid];
        bs[tid]  = beta[tid];
        bps[tid] = bp_[tid];
    }

    // ---- stage A_w (tf32) — shared by both groups, done once up front ----
    const float* Ag = g_A + (size_t)w * 4096;
    for (int idx = tid; idx < 1024; idx += 512) {
        float4 v = *(const float4*)(Ag + idx * 4);
        float* dst = As + (idx >> 4) * WS_STR + (idx & 15) * 4;
        dst[0] = __uint_as_float(f2tf(v.x));
        dst[1] = __uint_as_float(f2tf(v.y));
        dst[2] = __uint_as_float(f2tf(v.z));
        dst[3] = __uint_as_float(f2tf(v.w));
    }

    // ---- gather x window (64 tokens x 256 ch), coalesced float4, stride 260 ----
    for (int l = wid; l < 64; l += 8) {
        int tp = l >> 4, wi = l & 15;
        const float4* src = (const float4*)(x +
            ((size_t)(b * F_ + fi * TPc + tp) * K_ + nwi * WSZ + wi) * EDv);
        float4* dst = (float4*)(buf + l * XN_STR);
        dst[lane]      = src[lane];
        dst[lane + 32] = src[lane + 32];
    }
    __syncthreads();   // As + gs/bs/bps + both gathers visible

    // ---- LayerNorm in place (4 threads per token), tf32-round output ----
    {
        int t = tl >> 2, q = tl & 3;
        float* row = buf + t * XN_STR + q * 64;
        float s = 0.f, ss = 0.f;
#pragma unroll
        for (int i = 0; i < 64; i++) { float v = row[i]; s += v; ss = fmaf(v, v, ss); }
        s  += __shfl_xor_sync(0xffffffffu, s, 1);
        ss += __shfl_xor_sync(0xffffffffu, ss, 1);
        s  += __shfl_xor_sync(0xffffffffu, s, 2);
        ss += __shfl_xor_sync(0xffffffffu, ss, 2);
        float mu   = s * (1.f / 256.f);
        float var  = ss * (1.f / 256.f) - mu * mu;
        float rstd = rsqrtf(var + 1e-5f);
        const float* gg = gs + q * 64;
        const float* be = bs + q * 64;
#pragma unroll
        for (int i = 0; i < 64; i++) {
            float v = (row[i] - mu) * rstd * gg[i] + be[i];
            row[i] = __uint_as_float(f2tf(v));
        }
    }
    group_bar(g);   // xn ready for this group's GEMM1

    // ---- GEMM1: y(64x256) = xn(64x256) @ Wp^T; warp owns 32 output cols ----
    const int n0 = wid * 32;
    const int r4 = lane >> 2, c4 = lane & 3;
    float acc[4][4][4];
#pragma unroll
    for (int mt = 0; mt < 4; mt++)
#pragma unroll
        for (int nt = 0; nt < 4; nt++)
#pragma unroll
            for (int r = 0; r < 4; r++) acc[mt][nt][r] = 0.f;

    for (int kc = 0; kc < 4; kc++) {
        if (kc) __syncthreads();  // previous Wsm chunk fully consumed (both groups)
        // stage Wp chunk [o=0..255][k=kc*64 .. +63], tf32 — all 512 threads
        for (int idx = tid; idx < 256 * 16; idx += 512) {
            int o = idx >> 4, j = idx & 15;
            float4 v = *(const float4*)(Wp + (size_t)o * EDv + kc * 64 + j * 4);
            float* dst = Wsm + o * WS_STR + j * 4;
            dst[0] = __uint_as_float(f2tf(v.x));
            dst[1] = __uint_as_float(f2tf(v.y));
            dst[2] = __uint_as_float(f2tf(v.z));
            dst[3] = __uint_as_float(f2tf(v.w));
        }
        __syncthreads();

#pragma unroll
        for (int ks = 0; ks < 8; ks++) {
            int kb = kc * 64 + ks * 8;  // column in buf (xn)
            unsigned a[4][4];
#pragma unroll
            for (int mt = 0; mt < 4; mt++) {
                const float* base = buf + (mt * 16 + r4) * XN_STR + kb + c4;
                a[mt][0] = __float_as_uint(base[0]);
                a[mt][1] = __float_as_uint(base[8 * XN_STR]);
                a[mt][2] = __float_as_uint(base[4]);
                a[mt][3] = __float_as_uint(base[8 * XN_STR + 4]);
            }
            unsigned bb[4][2];
            int kl = ks * 8;
#pragma unroll
            for (int nt = 0; nt < 4; nt++) {
                const float* base = Wsm + (n0 + nt * 8 + r4) * WS_STR + kl + c4;
                bb[nt][0] = __float_as_uint(base[0]);
                bb[nt][1] = __float_as_uint(base[4]);
            }
#pragma unroll
            for (int mt = 0; mt < 4; mt++)
#pragma unroll
                for (int nt = 0; nt < 4; nt++)
                    mma_tf32(acc[mt][nt], a[mt][0], a[mt][1], a[mt][2], a[mt][3],
                             bb[nt][0], bb[nt][1]);
        }
    }

    group_bar(g);   // this group done reading xn -> safe to overwrite with y

    // ---- y -> buf (stride 264), add bias, tf32-round, float2 stores ----
#pragma unroll
    for (int mt = 0; mt < 4; mt++)
#pragma unroll
        for (int nt = 0; nt < 4; nt++) {
            int row = mt * 16 + r4;
            int col = n0 + nt * 8 + 2 * c4;
            float b0 = bps[col], b1 = bps[col + 1];
            float2 v01, v23;
            v01.x = __uint_as_float(f2tf(acc[mt][nt][0] + b0));
            v01.y = __uint_as_float(f2tf(acc[mt][nt][1] + b1));
            v23.x = __uint_as_float(f2tf(acc[mt][nt][2] + b0));
            v23.y = __uint_as_float(f2tf(acc[mt][nt][3] + b1));
            *(float2*)(buf + row * YZ_STR + col)       = v01;
            *(float2*)(buf + (row + 8) * YZ_STR + col) = v23;
        }
    group_bar(g);   // y visible to whole group

    // ---- GEMM2: z(64x256) = A_w(64x64) @ y(64x256) ----
#pragma unroll
    for (int mt = 0; mt < 4; mt++)
#pragma unroll
        for (int nt = 0; nt < 4; nt++)
#pragma unroll
            for (int r = 0; r < 4; r++) acc[mt][nt][r] = 0.f;

#pragma unroll
    for (int ks = 0; ks < 8; ks++) {
        int kb = ks * 8;
        unsigned a[4][4];
#pragma unroll
        for (int mt = 0; mt < 4; mt++) {
            const float* base = As + (mt * 16 + r4) * WS_STR + kb + c4;
            a[mt][0] = __float_as_uint(base[0]);
            a[mt][1] = __float_as_uint(base[8 * WS_STR]);
            a[mt][2] = __float_as_uint(base[4]);
            a[mt][3] = __float_as_uint(base[8 * WS_STR + 4]);
        }
        unsigned bb[4][2];
#pragma unroll
        for (int nt = 0; nt < 4; nt++) {
            const float* base = buf + (kb + c4) * YZ_STR + n0 + nt * 8 + r4;
            bb[nt][0] = __float_as_uint(base[0]);
            bb[nt][1] = __float_as_uint(base[4 * YZ_STR]);
        }
#pragma unroll
        for (int mt = 0; mt < 4; mt++)
#pragma unroll
            for (int nt = 0; nt < 4; nt++)
                mma_tf32(acc[mt][nt], a[mt][0], a[mt][1], a[mt][2], a[mt][3],
                         bb[nt][0], bb[nt][1]);
    }

    group_bar(g);   // group done reading y -> safe to overwrite with z

    // ---- z -> buf (stride 264), float2 stores ----
#pragma unroll
    for (int mt = 0; mt < 4; mt++)
#pragma unroll
        for (int nt = 0; nt < 4; nt++) {
            int row = mt * 16 + r4;
            int col = n0 + nt * 8 + 2 * c4;
            float2 v01, v23;
            v01.x = acc[mt][nt][0]; v01.y = acc[mt][nt][1];
            v23.x = acc[mt][nt][2]; v23.y = acc[mt][nt][3];
            *(float2*)(buf + row * YZ_STR + col)       = v01;
            *(float2*)(buf + (row + 8) * YZ_STR + col) = v23;
        }
    group_bar(g);   // z visible

    // ---- scatter with window_reverse, coalesced float4 ----
    for (int l = wid; l < 64; l += 8) {
        int tp = l >> 4, wi = l & 15;
        float4* dst = (float4*)(out +
            ((size_t)(b * F_ + fi * TPc + tp) * K_ + nwi * WSZ + wi) * EDv);
        const float4* src = (const float4*)(buf + l * YZ_STR);
        dst[lane]      = src[lane];
        dst[lane + 32] = src[lane + 32];
    }
}

// ---------------------------------------------------------------------------
// Launch
// ---------------------------------------------------------------------------
extern "C" void kernel_launch(void* const* d_in, const int* in_sizes, int n_in,
                              void* d_out, int out_size)
{
    const float* x     = (const float*)d_in[0];
    const float* gamma = (const float*)d_in[1];
    const float* beta  = (const float*)d_in[2];
    const float* Wp    = (const float*)d_in[3];
    const float* bp    = (const float*)d_in[4];
    const float* eb    = (const float*)d_in[5];
    const float* deg   = (const float*)d_in[6];
    float* out = (float*)d_out;

    compute_A_kernel<<<WTYPES, 256>>>(deg, eb);

    const int smem_bytes = (64 * WS_STR + 256 * WS_STR + 2 * 64 * YZ_STR +
                            3 * 256) * (int)sizeof(float);
    cudaFuncSetAttribute(fused_kernel,
                         cudaFuncAttributeMaxDynamicSharedMemorySize, smem_bytes);
    fused_kernel<<<NWIN / 2, 512, smem_bytes>>>(x, gamma, beta, Wp, bp, out);
}

// round 5
// speedup vs baseline: 1.9087x; 1.4586x over previous
#include <cuda_runtime.h>
#include <cuda_fp16.h>
#include <cstdint>

// Problem constants
#define TPc   4
#define WSZ   16
#define B_    8
#define F_    256
#define K_    64
#define EDv   256
#define NWIN  2048
#define WTYPES 256

// Shared memory layout (byte offsets, 256-thread fused kernel)
#define OFF_WSM 33792     // buf: 64 rows x 528B (264 halfs)
#define OFF_AS  70656     // Wsm: 256 rows x 144B (72 halfs)
#define OFF_GS  79872     // As:  64 rows x 144B
#define OFF_BS  80896
#define OFF_BPS 81920
#define OFF_MU  82944
#define OFF_RS  83200
#define OFF_GR  83456
#define SMEM_REQ 83712

#define BUF_S32 132       // buf row stride in b32 (264 halfs); 132 % 32 = 4
#define BUF_SB  528       // bytes;  528/16 = 33 (odd) -> ldmatrix conflict-free
#define W_S32   36        // Wsm/As row stride in b32 (72 halfs)
#define W_SB    144       // 144/16 = 9 (odd) -> ldmatrix conflict-free

// Scratch for A = deg @ edge_bias (4 MB). __device__ global: no allocation.
__device__ float g_A[WTYPES * 64 * 64];

// ---------------------------------------------------------------------------
// Kernel 0: A[w] = deg[w] @ eb[w] (fp32 FFMA, matches reference exactly)
// ---------------------------------------------------------------------------
__global__ __launch_bounds__(256) void compute_A_kernel(
    const float* __restrict__ deg, const float* __restrict__ eb)
{
    __shared__ float Ds[64][64];
    __shared__ float Es[64][68];
    int w = blockIdx.x, tid = threadIdx.x;
    const float* D = deg + (size_t)w * 4096;
    const float* E = eb  + (size_t)w * 4096;
    for (int idx = tid; idx < 4096; idx += 256) {
        Ds[idx >> 6][idx & 63] = D[idx];
        Es[idx >> 6][idx & 63] = E[idx];
    }
    __syncthreads();
    int p  = tid >> 2;
    int q0 = (tid & 3) * 16;
    float acc[16];
#pragma unroll
    for (int j = 0; j < 16; j++) acc[j] = 0.f;
    for (int k = 0; k < 64; k++) {
        float a = Ds[p][k];
#pragma unroll
        for (int j = 0; j < 16; j++) acc[j] = fmaf(a, Es[k][q0 + j], acc[j]);
    }
    float* Aout = g_A + (size_t)w * 4096 + p * 64 + q0;
#pragma unroll
    for (int j = 0; j < 16; j++) Aout[j] = acc[j];
}

// ---------------------------------------------------------------------------
// mma / ldmatrix helpers (all supported on baseline compute_103 PTX)
// ---------------------------------------------------------------------------
__device__ __forceinline__ uint32_t smem_u32(const void* p) {
    uint32_t a;
    asm("{ .reg .u64 t; cvta.to.shared.u64 t, %1; cvt.u32.u64 %0, t; }" : "=r"(a) : "l"(p));
    return a;
}

#define LDSM4(r0, r1, r2, r3, addr) \
    asm volatile("ldmatrix.sync.aligned.m8n8.x4.shared.b16 {%0,%1,%2,%3}, [%4];" \
                 : "=r"(r0), "=r"(r1), "=r"(r2), "=r"(r3) : "r"(addr))
#define LDSM4T(r0, r1, r2, r3, addr) \
    asm volatile("ldmatrix.sync.aligned.m8n8.x4.trans.shared.b16 {%0,%1,%2,%3}, [%4];" \
                 : "=r"(r0), "=r"(r1), "=r"(r2), "=r"(r3) : "r"(addr))

__device__ __forceinline__ void hmma(float c[4], const uint32_t a[4],
                                     uint32_t b0, uint32_t b1) {
    asm volatile(
        "mma.sync.aligned.m16n8k16.row.col.f32.f16.f16.f32 "
        "{%0,%1,%2,%3}, {%4,%5,%6,%7}, {%8,%9}, {%0,%1,%2,%3};"
        : "+f"(c[0]), "+f"(c[1]), "+f"(c[2]), "+f"(c[3])
        : "r"(a[0]), "r"(a[1]), "r"(a[2]), "r"(a[3]), "r"(b0), "r"(b1));
}

// ---------------------------------------------------------------------------
// Fused kernel: one 256-thread CTA per window (2 CTAs/SM).
//   LN(2-pass from gmem) -> buf(half) -> GEMM1 fp16 mma -> y(half, in buf)
//   -> GEMM2 (A_w @ y) -> direct float2 scatter to gmem (window_reverse)
// ---------------------------------------------------------------------------
__global__ __launch_bounds__(256, 2) void fused_fp16(
    const float* __restrict__ x, const float* __restrict__ gamma,
    const float* __restrict__ beta, const float* __restrict__ Wp,
    const float* __restrict__ bp_, float* __restrict__ out)
{
    extern __shared__ char smc[];
    __half2* buf2 = (__half2*)smc;
    __half2* wsm2 = (__half2*)(smc + OFF_WSM);
    __half2* as2  = (__half2*)(smc + OFF_AS);
    float* gs   = (float*)(smc + OFF_GS);
    float* bs   = (float*)(smc + OFF_BS);
    float* bps  = (float*)(smc + OFF_BPS);
    float* mu_s = (float*)(smc + OFF_MU);
    float* rs_s = (float*)(smc + OFF_RS);
    int*   grows= (int*)  (smc + OFF_GR);

    const uint32_t buf_u = smem_u32(smc);
    const uint32_t wsm_u = buf_u + OFF_WSM;
    const uint32_t as_u  = buf_u + OFF_AS;

    const int tid  = threadIdx.x;
    const int lane = tid & 31;
    const int wid  = tid >> 5;

    const int n   = blockIdx.x;
    const int b   = n >> 8;
    const int w   = n & 255;
    const int fi  = w >> 2;
    const int nwi = w & 3;

    gs[tid]  = gamma[tid];
    bs[tid]  = beta[tid];
    bps[tid] = bp_[tid];

    // ---- LN pass 1: per-token mean/rstd from gmem fp32 (4 threads/token) ----
    {
        int t = tid >> 2, q = tid & 3;
        int tp = t >> 4, wi2 = t & 15;
        int grow = (b * F_ + fi * TPc + tp) * K_ + nwi * WSZ + wi2;
        if (q == 0) grows[t] = grow;
        const float4* p = (const float4*)(x + (size_t)grow * EDv + q * 64);
        float s = 0.f, ss = 0.f;
#pragma unroll
        for (int i = 0; i < 16; i++) {
            float4 v = p[i];
            s += v.x + v.y + v.z + v.w;
            ss = fmaf(v.x, v.x, ss); ss = fmaf(v.y, v.y, ss);
            ss = fmaf(v.z, v.z, ss); ss = fmaf(v.w, v.w, ss);
        }
        s  += __shfl_xor_sync(0xffffffffu, s, 1);
        ss += __shfl_xor_sync(0xffffffffu, ss, 1);
        s  += __shfl_xor_sync(0xffffffffu, s, 2);
        ss += __shfl_xor_sync(0xffffffffu, ss, 2);
        if (q == 0) {
            float mu  = s * (1.f / 256.f);
            float var = ss * (1.f / 256.f) - mu * mu;
            mu_s[t] = mu;
            rs_s[t] = rsqrtf(var + 1e-5f);
        }
    }
    __syncthreads();

    // ---- LN pass 2: normalize (gmem reload, L2-hot) -> half2 into buf ----
    {
        float g0[4], g1[4], e0[4], e1[4];
#pragma unroll
        for (int j = 0; j < 4; j++) {
            int c = 64 * j + 2 * lane;
            g0[j] = gs[c]; g1[j] = gs[c + 1];
            e0[j] = bs[c]; e1[j] = bs[c + 1];
        }
#pragma unroll
        for (int t8 = 0; t8 < 8; t8++) {
            int t = wid * 8 + t8;
            float mu = mu_s[t], rstd = rs_s[t];
            const float* xr = x + (size_t)grows[t] * EDv;
#pragma unroll
            for (int j = 0; j < 4; j++) {
                float2 v = *(const float2*)(xr + 64 * j + 2 * lane);
                buf2[t * BUF_S32 + 32 * j + lane] = __floats2half2_rn(
                    (v.x - mu) * rstd * g0[j] + e0[j],
                    (v.y - mu) * rstd * g1[j] + e1[j]);
            }
        }
    }

    // ---- stage A_w as fp16 (warp w: rows w*8..w*8+7) ----
    {
        const float* Ag = g_A + (size_t)w * 4096;
#pragma unroll
        for (int r = 0; r < 8; r++) {
            int a = wid * 8 + r;
            float2 v = *(const float2*)(Ag + a * 64 + 2 * lane);
            as2[a * W_S32 + lane] = __floats2half2_rn(v.x, v.y);
        }
    }
    __syncthreads();

    const int n0 = wid * 32;
    const int r4 = lane >> 2, c4 = lane & 3;

    // ldmatrix lane->address parameters
    const int arow  = (lane & 7) + ((lane >> 3) & 1) * 8;  // A row within 16
    const int khi   = (lane >> 4) * 8;                     // +8 halfs (hi-k lanes)
    const int bnrow = ((lane >> 4) & 1) * 8 + (lane & 7);  // B n-row within 16
    const int bkhi  = ((lane >> 3) & 1) * 8;               // B k offset
    const int tkrow = ((lane >> 3) & 1) * 8 + (lane & 7);  // trans: k row within 16
    const int tnhi  = (lane >> 4) * 8;                     // trans: n +8

    float acc[4][4][4];
#pragma unroll
    for (int mt = 0; mt < 4; mt++)
#pragma unroll
        for (int nt = 0; nt < 4; nt++)
#pragma unroll
            for (int r = 0; r < 4; r++) acc[mt][nt][r] = 0.f;

    // ---- GEMM1: y(64x256) = xn @ Wp^T, fp16 mma, K chunked by 64 ----
    for (int kc = 0; kc < 4; kc++) {
        if (kc) __syncthreads();
        // stage Wp chunk [256 o][64 k] as half2 (warp: 32 rows, conflict-free)
#pragma unroll 4
        for (int r = 0; r < 32; r++) {
            int o = wid * 32 + r;
            float2 v = *(const float2*)(Wp + (size_t)o * EDv + kc * 64 + 2 * lane);
            wsm2[o * W_S32 + lane] = __floats2half2_rn(v.x, v.y);
        }
        __syncthreads();

#pragma unroll
        for (int ks = 0; ks < 4; ks++) {
            uint32_t a[4][4];
            uint32_t abase = buf_u + (uint32_t)arow * BUF_SB +
                             (uint32_t)(kc * 64 + ks * 16 + khi) * 2;
#pragma unroll
            for (int mt = 0; mt < 4; mt++)
                LDSM4(a[mt][0], a[mt][1], a[mt][2], a[mt][3],
                      abase + (uint32_t)(mt * 16) * BUF_SB);
            uint32_t bb[4][2];
#pragma unroll
            for (int ntp = 0; ntp < 2; ntp++) {
                uint32_t baddr = wsm_u + (uint32_t)(n0 + ntp * 16 + bnrow) * W_SB +
                                 (uint32_t)(ks * 16 + bkhi) * 2;
                LDSM4(bb[2 * ntp][0], bb[2 * ntp][1],
                      bb[2 * ntp + 1][0], bb[2 * ntp + 1][1], baddr);
            }
#pragma unroll
            for (int mt = 0; mt < 4; mt++)
#pragma unroll
                for (int nt = 0; nt < 4; nt++)
                    hmma(acc[mt][nt], a[mt], bb[nt][0], bb[nt][1]);
        }
    }
    __syncthreads();   // all warps done reading xn -> safe to overwrite buf

    // ---- epilogue1: y = acc + bias -> half2 into buf [tok][chan] ----
    {
        float p0[4], p1[4];
#pragma unroll
        for (int nt = 0; nt < 4; nt++) {
            int c = n0 + nt * 8 + 2 * c4;
            p0[nt] = bps[c]; p1[nt] = bps[c + 1];
        }
#pragma unroll
        for (int mt = 0; mt < 4; mt++)
#pragma unroll
            for (int nt = 0; nt < 4; nt++) {
                int row = mt * 16 + r4;
                int cc = (n0 + nt * 8 + 2 * c4) >> 1;
                buf2[row * BUF_S32 + cc] =
                    __floats2half2_rn(acc[mt][nt][0] + p0[nt], acc[mt][nt][1] + p1[nt]);
                buf2[(row + 8) * BUF_S32 + cc] =
                    __floats2half2_rn(acc[mt][nt][2] + p0[nt], acc[mt][nt][3] + p1[nt]);
            }
    }
    __syncthreads();

    // ---- GEMM2: z(64x256) = A_w(64x64) @ y ----
#pragma unroll
    for (int mt = 0; mt < 4; mt++)
#pragma unroll
        for (int nt = 0; nt < 4; nt++)
#pragma unroll
            for (int r = 0; r < 4; r++) acc[mt][nt][r] = 0.f;

#pragma unroll
    for (int ks = 0; ks < 4; ks++) {
        uint32_t a[4][4];
        uint32_t abase = as_u + (uint32_t)arow * W_SB + (uint32_t)(ks * 16 + khi) * 2;
#pragma unroll
        for (int mt = 0; mt < 4; mt++)
            LDSM4(a[mt][0], a[mt][1], a[mt][2], a[mt][3],
                  abase + (uint32_t)(mt * 16) * W_SB);
        uint32_t bb[4][2];
#pragma unroll
        for (int ntp = 0; ntp < 2; ntp++) {
            uint32_t baddr = buf_u + (uint32_t)(ks * 16 + tkrow) * BUF_SB +
                             (uint32_t)(n0 + ntp * 16 + tnhi) * 2;
            LDSM4T(bb[2 * ntp][0], bb[2 * ntp][1],
                   bb[2 * ntp + 1][0], bb[2 * ntp + 1][1], baddr);
        }
#pragma unroll
        for (int mt = 0; mt < 4; mt++)
#pragma unroll
            for (int nt = 0; nt < 4; nt++)
                hmma(acc[mt][nt], a[mt], bb[nt][0], bb[nt][1]);
    }

    // ---- epilogue2: direct float2 scatter to gmem (window_reverse) ----
#pragma unroll
    for (int mt = 0; mt < 4; mt++) {
        int t0 = mt * 16 + r4;
        float* o0 = out + (size_t)grows[t0] * EDv;
        float* o1 = out + (size_t)grows[t0 + 8] * EDv;
#pragma unroll
        for (int nt = 0; nt < 4; nt++) {
            int col = n0 + nt * 8 + 2 * c4;
            *(float2*)(o0 + col) = make_float2(acc[mt][nt][0], acc[mt][nt][1]);
            *(float2*)(o1 + col) = make_float2(acc[mt][nt][2], acc[mt][nt][3]);
        }
    }
}

// ---------------------------------------------------------------------------
// Launch
// ---------------------------------------------------------------------------
extern "C" void kernel_launch(void* const* d_in, const int* in_sizes, int n_in,
                              void* d_out, int out_size)
{
    const float* x     = (const float*)d_in[0];
    const float* gamma = (const float*)d_in[1];
    const float* beta  = (const float*)d_in[2];
    const float* Wp    = (const float*)d_in[3];
    const float* bp    = (const float*)d_in[4];
    const float* eb    = (const float*)d_in[5];
    const float* deg   = (const float*)d_in[6];
    float* out = (float*)d_out;

    compute_A_kernel<<<WTYPES, 256>>>(deg, eb);

    cudaFuncSetAttribute(fused_fp16,
                         cudaFuncAttributeMaxDynamicSharedMemorySize, SMEM_REQ);
    fused_fp16<<<NWIN, 256, SMEM_REQ>>>(x, gamma, beta, Wp, bp, out);
}